// round 15
// baseline (speedup 1.0000x reference)
#include <cuda_runtime.h>
#include <cuda_bf16.h>
#include <mma.h>
#include <cstddef>
#include <cstdint>

using namespace nvcuda;

#define NTOT   65536
#define CIN    128
#define CC     256
#define DSTATE 16
#define DCONV  4
#define DTRANK 16
#define GG     32
#define LL     2048
#define EE     131072

typedef __nv_bfloat16 bf16;

// ---------------------------------------------------------------------------
// Device scratch (fp32)
// ---------------------------------------------------------------------------
__device__ __align__(16) float g_xw [NTOT * CC];
__device__ __align__(16) float g_gcn[NTOT * CC];
__device__ __align__(16) float g_xz [NTOT * 2 * CC];
__device__ __align__(16) float g_bc [NTOT * 32];
__device__ __align__(16) float g_dt [NTOT * CC];
__device__ __align__(16) float g_hm [NTOT * CC];
__device__ __align__(16) float g_out2[NTOT * CC];
__device__ float g_deg[NTOT];
__device__ float g_dis[NTOT];
__device__ float g_stats1[2 * CC];
__device__ float g_stats2[2 * CC];
__device__ float g_stats3[2 * CC];

// bf16 hi/lo split activations
__device__ __align__(16) bf16 g_nf_h [NTOT * CIN];
__device__ __align__(16) bf16 g_nf_l [NTOT * CIN];
__device__ __align__(16) bf16 g_x0_h [NTOT * CC];
__device__ __align__(16) bf16 g_x0_l [NTOT * CC];
__device__ __align__(16) bf16 g_xcv_h[NTOT * CC];
__device__ __align__(16) bf16 g_xcv_l[NTOT * CC];
__device__ __align__(16) bf16 g_y_h  [NTOT * CC];
__device__ __align__(16) bf16 g_y_l  [NTOT * CC];
__device__ __align__(16) bf16 g_o1_h [NTOT * CC];
__device__ __align__(16) bf16 g_o1_l [NTOT * CC];
__device__ __align__(16) bf16 g_mlp_h[NTOT * 2 * CC];   // single bf16 (no lo)

// bf16 hi/lo split weights, all [K, N] layout
__device__ __align__(16) bf16 g_win_h [CIN * CC];
__device__ __align__(16) bf16 g_win_l [CIN * CC];
__device__ __align__(16) bf16 g_wgcn_h[CC * CC];
__device__ __align__(16) bf16 g_wgcn_l[CC * CC];
__device__ __align__(16) bf16 g_wip_h [CC * 2 * CC];
__device__ __align__(16) bf16 g_wip_l [CC * 2 * CC];
__device__ __align__(16) bf16 g_m_h   [CC * CC];
__device__ __align__(16) bf16 g_m_l   [CC * CC];
__device__ __align__(16) bf16 g_wop_h [CC * CC];
__device__ __align__(16) bf16 g_wop_l [CC * CC];
__device__ __align__(16) bf16 g_wm1_h [CC * 2 * CC];
__device__ __align__(16) bf16 g_wm1_l [CC * 2 * CC];
__device__ __align__(16) bf16 g_wm2_h [2 * CC * CC];
__device__ __align__(16) bf16 g_wm2_l [2 * CC * CC];

__device__ __forceinline__ float act_softplus(float v) {
    return (v > 20.f) ? v : log1pf(__expf(v));
}

__device__ __forceinline__ void split2(float v, bf16& h, bf16& l) {
    h = __float2bfloat16_rn(v);
    l = __float2bfloat16_rn(v - __bfloat162float(h));
}

__device__ __forceinline__ uint32_t smem_u32(const void* p) {
    uint32_t a;
    asm("{ .reg .u64 t; cvta.to.shared.u64 t, %1; cvt.u32.u64 %0, t; }" : "=r"(a) : "l"(p));
    return a;
}

__device__ __forceinline__ float4 recon4(const bf16* h, const bf16* l, size_t idx) {
    __nv_bfloat162 ha = *(const __nv_bfloat162*)&h[idx];
    __nv_bfloat162 hb = *(const __nv_bfloat162*)&h[idx + 2];
    __nv_bfloat162 la = *(const __nv_bfloat162*)&l[idx];
    __nv_bfloat162 lb = *(const __nv_bfloat162*)&l[idx + 2];
    float4 r;
    r.x = __bfloat162float(__low2bfloat16(ha))  + __bfloat162float(__low2bfloat16(la));
    r.y = __bfloat162float(__high2bfloat16(ha)) + __bfloat162float(__high2bfloat16(la));
    r.z = __bfloat162float(__low2bfloat16(hb))  + __bfloat162float(__low2bfloat16(lb));
    r.w = __bfloat162float(__high2bfloat16(hb)) + __bfloat162float(__high2bfloat16(lb));
    return r;
}

// ---------------------------------------------------------------------------
// Split-bf16 tensor-core GEMM: D = AhBh + AhBl (+ AlBh if AHL), fp32 accum.
// Block 128x128, 256 threads (2x4 warps), warp tile 64x32, m16n16k16.
// cp.async 2-stage, K-tile 32. A [M,K], B [K,N].
// RES: 0 none, 1 fp32, 2 bf16 h/l pair.
// OUTB1: single-bf16 output. STATS: fused per-column sum/sumsq.
// ---------------------------------------------------------------------------
#define KT 32
#define A_LDE 40
#define B_LDE 136
#define A_TILE_EL (128 * A_LDE)
#define B_TILE_EL (KT * B_LDE)
#define STAGE_EL (2 * A_TILE_EL + 2 * B_TILE_EL)
#define TG_SMEM_BYTES (2 * STAGE_EL * 2)       // 75776 B
#define STG_LD 36
#define PART_OFF 8192

template <int ACT, bool HASBIAS, int RES, bool OUTF32, bool OUTSPLIT, bool OUTB1,
          bool STATS, bool AHL>
__global__ void __launch_bounds__(256, 2)
bgemm_k(const bf16* __restrict__ Ah, const bf16* __restrict__ Al,
        const bf16* __restrict__ Bh, const bf16* __restrict__ Bl,
        const float* __restrict__ bias,
        const float* __restrict__ resF,
        const bf16* __restrict__ resH, const bf16* __restrict__ resL,
        float* __restrict__ outF, bf16* __restrict__ outH, bf16* __restrict__ outL,
        float* __restrict__ stats,
        int M, int Nout, int K)
{
    extern __shared__ bf16 smem[];

    const int tid = threadIdx.x;
    const int warp = tid >> 5;
    const int lane = tid & 31;
    const int warp_m = warp >> 2;
    const int warp_n = warp & 3;
    const int m0 = blockIdx.y * 128;
    const int n0 = blockIdx.x * 128;

    wmma::fragment<wmma::accumulator, 16, 16, 16, float> cf[4][2];
#pragma unroll
    for (int i = 0; i < 4; i++)
#pragma unroll
        for (int j = 0; j < 2; j++) wmma::fill_fragment(cf[i][j], 0.f);

    auto issue_tile = [&](int kt, int buf) {
        bf16* sAh = smem + buf * STAGE_EL;
        bf16* sAl = sAh + A_TILE_EL;
        bf16* sBh = sAl + A_TILE_EL;
        bf16* sBl = sBh + B_TILE_EL;
#pragma unroll
        for (int it = 0; it < 2; it++) {
            int i = it * 256 + tid;
            int r = i >> 2, c = i & 3;
            size_t src = (size_t)(m0 + r) * K + kt + c * 8;
            asm volatile("cp.async.ca.shared.global [%0], [%1], 16;"
                         :: "r"(smem_u32(&sAh[r * A_LDE + c * 8])), "l"(Ah + src));
            if (AHL)
                asm volatile("cp.async.ca.shared.global [%0], [%1], 16;"
                             :: "r"(smem_u32(&sAl[r * A_LDE + c * 8])), "l"(Al + src));
        }
#pragma unroll
        for (int it = 0; it < 2; it++) {
            int i = it * 256 + tid;
            int r = i >> 4, c = i & 15;
            size_t src = (size_t)(kt + r) * Nout + n0 + c * 8;
            asm volatile("cp.async.ca.shared.global [%0], [%1], 16;"
                         :: "r"(smem_u32(&sBh[r * B_LDE + c * 8])), "l"(Bh + src));
            asm volatile("cp.async.ca.shared.global [%0], [%1], 16;"
                         :: "r"(smem_u32(&sBl[r * B_LDE + c * 8])), "l"(Bl + src));
        }
        asm volatile("cp.async.commit_group;");
    };

    const int nk = K / KT;
    issue_tile(0, 0);

    for (int i = 0; i < nk; i++) {
        const bool has_next = (i + 1) < nk;
        if (has_next) issue_tile((i + 1) * KT, (i + 1) & 1);

        if (has_next) asm volatile("cp.async.wait_group 1;");
        else          asm volatile("cp.async.wait_group 0;");
        __syncthreads();

        const bf16* sAh = smem + (i & 1) * STAGE_EL;
        const bf16* sAl = sAh + A_TILE_EL;
        const bf16* sBh = sAl + A_TILE_EL;
        const bf16* sBl = sBh + B_TILE_EL;

#pragma unroll
        for (int ks = 0; ks < KT; ks += 16) {
            wmma::fragment<wmma::matrix_b, 16, 16, 16, bf16, wmma::row_major> bh[2], bl[2];
#pragma unroll
            for (int j = 0; j < 2; j++) {
                wmma::load_matrix_sync(bh[j], &sBh[ks * B_LDE + warp_n * 32 + j * 16], B_LDE);
                wmma::load_matrix_sync(bl[j], &sBl[ks * B_LDE + warp_n * 32 + j * 16], B_LDE);
            }
#pragma unroll
            for (int x = 0; x < 4; x++) {
                wmma::fragment<wmma::matrix_a, 16, 16, 16, bf16, wmma::row_major> ah, al;
                wmma::load_matrix_sync(ah, &sAh[(warp_m * 64 + x * 16) * A_LDE + ks], A_LDE);
                if (AHL)
                    wmma::load_matrix_sync(al, &sAl[(warp_m * 64 + x * 16) * A_LDE + ks], A_LDE);
#pragma unroll
                for (int j = 0; j < 2; j++) {
                    wmma::mma_sync(cf[x][j], ah, bh[j], cf[x][j]);
                    wmma::mma_sync(cf[x][j], ah, bl[j], cf[x][j]);
                    if (AHL) wmma::mma_sync(cf[x][j], al, bh[j], cf[x][j]);
                }
            }
        }
        __syncthreads();
    }

    float* fs = reinterpret_cast<float*>(smem);
    float* stg = fs + warp * (16 * STG_LD);
    float* mp = fs + PART_OFF + tid * 33;
    const int erow = lane >> 1;
    const int ecol0 = (lane & 1) * 16;

    if (STATS) {
#pragma unroll
        for (int i = 0; i < 32; i++) mp[i] = 0.f;
    }

#pragma unroll
    for (int x = 0; x < 4; x++) {
        wmma::store_matrix_sync(stg,      cf[x][0], STG_LD, wmma::mem_row_major);
        wmma::store_matrix_sync(stg + 16, cf[x][1], STG_LD, wmma::mem_row_major);
        __syncwarp();
        const int grow = m0 + warp_m * 64 + x * 16 + erow;
#pragma unroll
        for (int c4 = 0; c4 < 16; c4 += 4) {
            const int lcol = ecol0 + c4;
            const int gcol = n0 + warp_n * 32 + lcol;
            float4 v = *(float4*)&stg[erow * STG_LD + lcol];
            if (HASBIAS) {
                float4 bb = *(const float4*)&bias[gcol];
                v.x += bb.x; v.y += bb.y; v.z += bb.z; v.w += bb.w;
            }
            if (ACT == 1) {
                v.x = fmaxf(v.x, 0.f); v.y = fmaxf(v.y, 0.f);
                v.z = fmaxf(v.z, 0.f); v.w = fmaxf(v.w, 0.f);
            } else if (ACT == 2) {
                v.x = act_softplus(v.x); v.y = act_softplus(v.y);
                v.z = act_softplus(v.z); v.w = act_softplus(v.w);
            }
            const size_t oidx = (size_t)grow * Nout + gcol;
            if (RES == 1) {
                float4 rr = *(const float4*)&resF[oidx];
                v.x += rr.x; v.y += rr.y; v.z += rr.z; v.w += rr.w;
            } else if (RES == 2) {
                float4 rr = recon4(resH, resL, oidx);
                v.x += rr.x; v.y += rr.y; v.z += rr.z; v.w += rr.w;
            }
            if (STATS) {
                mp[c4 + 0] += v.x; mp[c4 + 1] += v.y;
                mp[c4 + 2] += v.z; mp[c4 + 3] += v.w;
                mp[16 + c4 + 0] += v.x * v.x; mp[16 + c4 + 1] += v.y * v.y;
                mp[16 + c4 + 2] += v.z * v.z; mp[16 + c4 + 3] += v.w * v.w;
            }
            if (OUTF32) *(float4*)&outF[oidx] = v;
            if (OUTSPLIT) {
                bf16 h0, l0, h1, l1, h2, l2, h3, l3;
                split2(v.x, h0, l0); split2(v.y, h1, l1);
                split2(v.z, h2, l2); split2(v.w, h3, l3);
                __nv_bfloat162 ha = {h0, h1}, hb = {h2, h3};
                __nv_bfloat162 la = {l0, l1}, lb = {l2, l3};
                *(__nv_bfloat162*)&outH[oidx]     = ha;
                *(__nv_bfloat162*)&outH[oidx + 2] = hb;
                *(__nv_bfloat162*)&outL[oidx]     = la;
                *(__nv_bfloat162*)&outL[oidx + 2] = lb;
            }
            if (OUTB1) {
                __nv_bfloat162 ha = __floats2bfloat162_rn(v.x, v.y);
                __nv_bfloat162 hb = __floats2bfloat162_rn(v.z, v.w);
                *(__nv_bfloat162*)&outH[oidx]     = ha;
                *(__nv_bfloat162*)&outH[oidx + 2] = hb;
            }
        }
        __syncwarp();
    }

    if (STATS) {
        __syncthreads();
        const int c = tid >> 1, s = tid & 1;
        const int wn = c >> 5, ch = (c >> 4) & 1, li = c & 15;
        float tot = 0.f;
#pragma unroll
        for (int wm = 0; wm < 2; wm++)
#pragma unroll
            for (int er = 0; er < 16; er++) {
                int ct = (wm * 4 + wn) * 32 + er * 2 + ch;
                tot += fs[PART_OFF + ct * 33 + s * 16 + li];
            }
        atomicAdd(&stats[s * CC + n0 + c], tot);
    }
}

// ---------------------------------------------------------------------------
// Split kernels
// ---------------------------------------------------------------------------
__global__ void split_arr(const float* __restrict__ src, bf16* __restrict__ oh,
                          bf16* __restrict__ ol, int n4) {
    int i = blockIdx.x * 256 + threadIdx.x;
    if (i >= n4) return;
    float4 v = *(const float4*)&src[(size_t)i * 4];
    size_t b = (size_t)i * 4;
    split2(v.x, oh[b + 0], ol[b + 0]);
    split2(v.y, oh[b + 1], ol[b + 1]);
    split2(v.z, oh[b + 2], ol[b + 2]);
    split2(v.w, oh[b + 3], ol[b + 3]);
}

__global__ void w_split_t(const float* __restrict__ W, bf16* __restrict__ oh,
                          bf16* __restrict__ ol, int Kk, int Nn) {
    int idx = blockIdx.x * 256 + threadIdx.x;
    if (idx >= Kk * Nn) return;
    int k = idx / Nn, n = idx % Nn;
    split2(W[(size_t)n * Kk + k], oh[idx], ol[idx]);
}

__global__ void make_M_kernel(const float* __restrict__ W_dt,
                              const float* __restrict__ W_xproj) {
    int c = blockIdx.x, d = threadIdx.x;
    float s = 0.f;
#pragma unroll
    for (int r = 0; r < DTRANK; r++)
        s += W_dt[c * DTRANK + r] * W_xproj[r * CC + d];
    split2(s, g_m_h[d * CC + c], g_m_l[d * CC + c]);
}

// ---------------------------------------------------------------------------
// GCN helpers
// ---------------------------------------------------------------------------
__global__ void deg_kernel(const int* __restrict__ dst) {
    int e = blockIdx.x * 256 + threadIdx.x;
    if (e < EE) atomicAdd(&g_deg[dst[e]], 1.0f);
}

__global__ void dis_kernel() {
    int n = blockIdx.x * 256 + threadIdx.x;
    if (n < NTOT) g_dis[n] = rsqrtf(g_deg[n] + 1.0f);
}

__global__ void init_gcn_kernel(const float* __restrict__ b_gcn) {
    int idx = blockIdx.x * 256 + threadIdx.x;
    int n = idx >> 6;
    int c4 = (idx & 63) << 2;
    float w = g_dis[n]; w *= w;
    float4 xv = *(const float4*)&g_xw[(size_t)n * CC + c4];
    float4 bb = *(const float4*)&b_gcn[c4];
    float4 o;
    o.x = bb.x + xv.x * w; o.y = bb.y + xv.y * w;
    o.z = bb.z + xv.z * w; o.w = bb.w + xv.w * w;
    *(float4*)&g_gcn[(size_t)n * CC + c4] = o;
}

__global__ void scatter_kernel(const int* __restrict__ src, const int* __restrict__ dst) {
    int t = blockIdx.x * 256 + threadIdx.x;
    int e = t >> 6;
    int c4 = (t & 63) << 2;
    int s = src[e], d = dst[e];
    float w = g_dis[s] * g_dis[d];
    float4 v = *(const float4*)&g_xw[(size_t)s * CC + c4];
    float* o = &g_gcn[(size_t)d * CC + c4];
    asm volatile("red.global.add.v4.f32 [%0], {%1, %2, %3, %4};"
                 :: "l"(o), "f"(v.x * w), "f"(v.y * w), "f"(v.z * w), "f"(v.w * w)
                 : "memory");
}

// ---------------------------------------------------------------------------
// BatchNorm
// ---------------------------------------------------------------------------
template <bool HASB2>
__global__ void bn_reduce(const float* __restrict__ A,
                          const bf16* __restrict__ Bh, const bf16* __restrict__ Bl,
                          float* __restrict__ stats) {
    int c = threadIdx.x;
    int r0 = blockIdx.x * 256;
    float s = 0.f, s2 = 0.f;
    for (int r = 0; r < 256; r++) {
        size_t idx = (size_t)(r0 + r) * CC + c;
        float v = A[idx];
        if (HASB2)
            v += __bfloat162float(Bh[idx]) + __bfloat162float(Bl[idx]);
        s += v; s2 += v * v;
    }
    atomicAdd(&stats[c], s);
    atomicAdd(&stats[CC + c], s2);
}

// Fused BN1+BN2 apply: o1 = norm1(gcn + x0) + norm2(hm)  [hm has +x0]
__global__ void bn12_apply(const float* __restrict__ gcn,
                           const bf16* __restrict__ x0h, const bf16* __restrict__ x0l,
                           const float* __restrict__ hm,
                           const float* __restrict__ g1, const float* __restrict__ b1,
                           const float* __restrict__ g2, const float* __restrict__ b2,
                           const float* __restrict__ st1, const float* __restrict__ st2,
                           bf16* __restrict__ oh, bf16* __restrict__ ol)
{
    int idx = blockIdx.x * 256 + threadIdx.x;
    int c4 = (idx & 63) << 2;
    const float invN = 1.0f / NTOT;

    float4 a = *(const float4*)&gcn[(size_t)idx * 4];
    float4 x = recon4(x0h, x0l, (size_t)idx * 4);
    a.x += x.x; a.y += x.y; a.z += x.z; a.w += x.w;
    float4 b = *(const float4*)&hm[(size_t)idx * 4];

    float4 sm1 = *(const float4*)&st1[c4];
    float4 sq1 = *(const float4*)&st1[CC + c4];
    float4 sm2 = *(const float4*)&st2[c4];
    float4 sq2 = *(const float4*)&st2[CC + c4];
    float4 gm1 = *(const float4*)&g1[c4];
    float4 bt1 = *(const float4*)&b1[c4];
    float4 gm2 = *(const float4*)&g2[c4];
    float4 bt2 = *(const float4*)&b2[c4];

    float4 o;
    {
        float m1 = sm1.x * invN, m2 = sm2.x * invN;
        float r1 = rsqrtf(sq1.x * invN - m1 * m1 + 1e-5f);
        float r2 = rsqrtf(sq2.x * invN - m2 * m2 + 1e-5f);
        o.x = (a.x - m1) * r1 * gm1.x + bt1.x + (b.x - m2) * r2 * gm2.x + bt2.x;
    }
    {
        float m1 = sm1.y * invN, m2 = sm2.y * invN;
        float r1 = rsqrtf(sq1.y * invN - m1 * m1 + 1e-5f);
        float r2 = rsqrtf(sq2.y * invN - m2 * m2 + 1e-5f);
        o.y = (a.y - m1) * r1 * gm1.y + bt1.y + (b.y - m2) * r2 * gm2.y + bt2.y;
    }
    {
        float m1 = sm1.z * invN, m2 = sm2.z * invN;
        float r1 = rsqrtf(sq1.z * invN - m1 * m1 + 1e-5f);
        float r2 = rsqrtf(sq2.z * invN - m2 * m2 + 1e-5f);
        o.z = (a.z - m1) * r1 * gm1.z + bt1.z + (b.z - m2) * r2 * gm2.z + bt2.z;
    }
    {
        float m1 = sm1.w * invN, m2 = sm2.w * invN;
        float r1 = rsqrtf(sq1.w * invN - m1 * m1 + 1e-5f);
        float r2 = rsqrtf(sq2.w * invN - m2 * m2 + 1e-5f);
        o.w = (a.w - m1) * r1 * gm1.w + bt1.w + (b.w - m2) * r2 * gm2.w + bt2.w;
    }

    size_t base = (size_t)idx * 4;
    split2(o.x, oh[base + 0], ol[base + 0]);
    split2(o.y, oh[base + 1], ol[base + 1]);
    split2(o.z, oh[base + 2], ol[base + 2]);
    split2(o.w, oh[base + 3], ol[base + 3]);
}

__global__ void bn3_apply(const float* __restrict__ A,
                          const float* __restrict__ gamma, const float* __restrict__ beta,
                          const float* __restrict__ stats, float* __restrict__ out)
{
    int idx = blockIdx.x * 256 + threadIdx.x;
    int c4 = (idx & 63) << 2;
    const float invN = 1.0f / NTOT;
    float4 v = *(const float4*)&A[(size_t)idx * 4];
    float4 sm = *(const float4*)&stats[c4];
    float4 sq = *(const float4*)&stats[CC + c4];
    float4 gm = *(const float4*)&gamma[c4];
    float4 bt = *(const float4*)&beta[c4];
    float4 m, r, o;
    m.x = sm.x * invN; m.y = sm.y * invN; m.z = sm.z * invN; m.w = sm.w * invN;
    r.x = rsqrtf(sq.x * invN - m.x * m.x + 1e-5f);
    r.y = rsqrtf(sq.y * invN - m.y * m.y + 1e-5f);
    r.z = rsqrtf(sq.z * invN - m.z * m.z + 1e-5f);
    r.w = rsqrtf(sq.w * invN - m.w * m.w + 1e-5f);
    o.x = fmaxf((v.x - m.x) * r.x * gm.x + bt.x, 0.f);
    o.y = fmaxf((v.y - m.y) * r.y * gm.y + bt.y, 0.f);
    o.z = fmaxf((v.z - m.z) * r.z * gm.z + bt.z, 0.f);
    o.w = fmaxf((v.w - m.w) * r.w * gm.w + bt.w, 0.f);
    *(float4*)&out[(size_t)idx * 4] = o;
}

// ---------------------------------------------------------------------------
// Mamba pieces
// ---------------------------------------------------------------------------
__global__ void conv_silu_kernel(const float* __restrict__ conv_w,
                                 const float* __restrict__ conv_b) {
    int idx = blockIdx.x * 256 + threadIdx.x;
    int n = idx >> 8;
    int c = idx & 255;
    int l = n & (LL - 1);
    float acc = conv_b[c];
#pragma unroll
    for (int kk = 0; kk < DCONV; kk++) {
        int l2 = l + kk - (DCONV - 1);
        if (l2 >= 0)
            acc += g_xz[(size_t)(n + kk - (DCONV - 1)) * (2 * CC) + c] * conv_w[c * DCONV + kk];
    }
    float sg = __fdividef(1.f, 1.f + __expf(-acc));
    float r = acc * sg;
    size_t o = (size_t)n * CC + c;
    split2(r, g_xcv_h[o], g_xcv_l[o]);
}

__global__ void __launch_bounds__(256) gemm_bc_kernel(const float* __restrict__ W) {
    __shared__ float Ws[32][257];
    __shared__ float xs[8][256];
    int tid = threadIdx.x;
    for (int i = tid; i < 32 * 256; i += 256) Ws[i >> 8][i & 255] = W[i];
    int r0 = blockIdx.x * 8;
    for (int i = tid; i < 8 * 256; i += 256) {
        size_t ii = (size_t)(r0 + (i >> 8)) * CC + (i & 255);
        xs[i >> 8][i & 255] = __bfloat162float(g_xcv_h[ii]) + __bfloat162float(g_xcv_l[ii]);
    }
    __syncthreads();
    int r = tid >> 5, j = tid & 31;
    float acc = 0.f;
#pragma unroll 8
    for (int k = 0; k < 256; k++) acc = fmaf(xs[r][k], Ws[j][k], acc);
    g_bc[(size_t)(r0 + r) * 32 + j] = acc;
}

__global__ void __launch_bounds__(1024) scan_kernel(const float* __restrict__ A_log,
                                                    const float* __restrict__ Dp) {
    int g = blockIdx.x >> 2;
    int cb = blockIdx.x & 3;
    int tid = threadIdx.x;
    int chl = tid >> 4;
    int n = tid & 15;
    int d = cb * 64 + chl;

    float An = -expf(A_log[d * DSTATE + n]);
    float Dd = Dp[d];

    const float* dtp = g_dt + (size_t)g * LL * CC + d;
    const bf16* xph  = g_xcv_h + (size_t)g * LL * CC + d;
    const bf16* xpl  = g_xcv_l + (size_t)g * LL * CC + d;
    const float* bp  = g_bc + (size_t)g * LL * 32 + n;
    const float* cp  = bp + 16;
    const float* zp  = g_xz + (size_t)g * LL * (2 * CC) + CC + d;
    bf16* yh = g_y_h + (size_t)g * LL * CC + d;
    bf16* yl = g_y_l + (size_t)g * LL * CC + d;

    float h = 0.f;
    float dtv = dtp[0];
    float xv = __bfloat162float(xph[0]) + __bfloat162float(xpl[0]);
    float Bn = bp[0], Cn = cp[0];
    float zv = (n == 0) ? zp[0] : 0.f;

    for (int t = 0; t < LL; t++) {
        float dtn = 0.f, xn = 0.f, Bn2 = 0.f, Cn2 = 0.f, zn = 0.f;
        if (t + 1 < LL) {
            dtn = dtp[(size_t)(t + 1) * CC];
            xn  = __bfloat162float(xph[(size_t)(t + 1) * CC]) +
                  __bfloat162float(xpl[(size_t)(t + 1) * CC]);
            Bn2 = bp[(size_t)(t + 1) * 32];
            Cn2 = cp[(size_t)(t + 1) * 32];
            if (n == 0) zn = zp[(size_t)(t + 1) * (2 * CC)];
        }
        float e = __expf(dtv * An);
        float dx = dtv * xv;
        h = fmaf(e, h, dx * Bn);
        float p = h * Cn;
        p += __shfl_xor_sync(0xffffffffu, p, 1);
        p += __shfl_xor_sync(0xffffffffu, p, 2);
        p += __shfl_xor_sync(0xffffffffu, p, 4);
        p += __shfl_xor_sync(0xffffffffu, p, 8);
        if (n == 0) {
            float sg = __fdividef(zv, 1.f + __expf(-zv));
            float yv = (p + xv * Dd) * sg;
            bf16 hh, lll;
            split2(yv, hh, lll);
            yh[(size_t)t * CC] = hh;
            yl[(size_t)t * CC] = lll;
        }
        dtv = dtn; xv = xn; Bn = Bn2; Cn = Cn2; zv = zn;
    }
}

// ---------------------------------------------------------------------------
// Host launcher
// ---------------------------------------------------------------------------
extern "C" void kernel_launch(void* const* d_in, const int* in_sizes, int n_in,
                              void* d_out, int out_size)
{
    const float* node_features = (const float*)d_in[0];
    const int*   edge_index    = (const int*)d_in[1];
    const float* W_in    = (const float*)d_in[3];
    const float* b_in    = (const float*)d_in[4];
    const float* W_gcn   = (const float*)d_in[5];
    const float* b_gcn   = (const float*)d_in[6];
    const float* gamma1  = (const float*)d_in[7];
    const float* beta1   = (const float*)d_in[8];
    const float* gamma2  = (const float*)d_in[9];
    const float* beta2   = (const float*)d_in[10];
    const float* gamma3  = (const float*)d_in[11];
    const float* beta3   = (const float*)d_in[12];
    const float* W_inproj = (const float*)d_in[13];
    const float* conv_w  = (const float*)d_in[14];
    const float* conv_b  = (const float*)d_in[15];
    const float* W_xproj = (const float*)d_in[16];
    const float* W_dt    = (const float*)d_in[17];
    const float* b_dt    = (const float*)d_in[18];
    const float* A_log   = (const float*)d_in[19];
    const float* Dp      = (const float*)d_in[20];
    const float* W_outproj = (const float*)d_in[21];
    const float* W_mlp1  = (const float*)d_in[22];
    const float* b_mlp1  = (const float*)d_in[23];
    const float* W_mlp2  = (const float*)d_in[24];
    const float* b_mlp2  = (const float*)d_in[25];
    float* out = (float*)d_out;

    const int* e_src = edge_index;
    const int* e_dst = edge_index + EE;

    float *p_xw, *p_xz, *p_dt, *p_hm, *p_out2, *p_gcn, *p_deg;
    float *p_st1, *p_st2, *p_st3;
    bf16 *p_nfh, *p_nfl, *p_x0h, *p_x0l, *p_xch, *p_xcl, *p_yh, *p_yl,
         *p_o1h, *p_o1l, *p_mph;
    bf16 *p_winh, *p_winl, *p_wgh, *p_wgl, *p_wiph, *p_wipl, *p_mh, *p_ml,
         *p_woph, *p_wopl, *p_wm1h, *p_wm1l, *p_wm2h, *p_wm2l;
    cudaGetSymbolAddress((void**)&p_xw,   g_xw);
    cudaGetSymbolAddress((void**)&p_xz,   g_xz);
    cudaGetSymbolAddress((void**)&p_dt,   g_dt);
    cudaGetSymbolAddress((void**)&p_hm,   g_hm);
    cudaGetSymbolAddress((void**)&p_out2, g_out2);
    cudaGetSymbolAddress((void**)&p_gcn,  g_gcn);
    cudaGetSymbolAddress((void**)&p_deg,  g_deg);
    cudaGetSymbolAddress((void**)&p_st1,  g_stats1);
    cudaGetSymbolAddress((void**)&p_st2,  g_stats2);
    cudaGetSymbolAddress((void**)&p_st3,  g_stats3);
    cudaGetSymbolAddress((void**)&p_nfh,  g_nf_h);
    cudaGetSymbolAddress((void**)&p_nfl,  g_nf_l);
    cudaGetSymbolAddress((void**)&p_x0h,  g_x0_h);
    cudaGetSymbolAddress((void**)&p_x0l,  g_x0_l);
    cudaGetSymbolAddress((void**)&p_xch,  g_xcv_h);
    cudaGetSymbolAddress((void**)&p_xcl,  g_xcv_l);
    cudaGetSymbolAddress((void**)&p_yh,   g_y_h);
    cudaGetSymbolAddress((void**)&p_yl,   g_y_l);
    cudaGetSymbolAddress((void**)&p_o1h,  g_o1_h);
    cudaGetSymbolAddress((void**)&p_o1l,  g_o1_l);
    cudaGetSymbolAddress((void**)&p_mph,  g_mlp_h);
    cudaGetSymbolAddress((void**)&p_winh, g_win_h);
    cudaGetSymbolAddress((void**)&p_winl, g_win_l);
    cudaGetSymbolAddress((void**)&p_wgh,  g_wgcn_h);
    cudaGetSymbolAddress((void**)&p_wgl,  g_wgcn_l);
    cudaGetSymbolAddress((void**)&p_wiph, g_wip_h);
    cudaGetSymbolAddress((void**)&p_wipl, g_wip_l);
    cudaGetSymbolAddress((void**)&p_mh,   g_m_h);
    cudaGetSymbolAddress((void**)&p_ml,   g_m_l);
    cudaGetSymbolAddress((void**)&p_woph, g_wop_h);
    cudaGetSymbolAddress((void**)&p_wopl, g_wop_l);
    cudaGetSymbolAddress((void**)&p_wm1h, g_wm1_h);
    cudaGetSymbolAddress((void**)&p_wm1l, g_wm1_l);
    cudaGetSymbolAddress((void**)&p_wm2h, g_wm2_h);
    cudaGetSymbolAddress((void**)&p_wm2l, g_wm2_l);

    // <ACT, HASBIAS, RES, OUTF32, OUTSPLIT, OUTB1, STATS, AHL>
    auto* gV1 = bgemm_k<0, true,  0, false, true,  false, false, true >;  // x0 split
    auto* gV2 = bgemm_k<0, false, 0, true,  false, false, false, true >;  // xw, xz
    auto* gV3 = bgemm_k<2, true,  0, true,  false, false, false, true >;  // dt
    auto* gV4 = bgemm_k<0, false, 2, true,  false, false, true,  true >;  // outproj + x0 + st2
    auto* gV5 = bgemm_k<1, true,  0, false, false, true,  false, true >;  // mlp1 -> single bf16
    auto* gV6 = bgemm_k<0, true,  2, true,  false, false, true,  false>;  // mlp2 (A single) + o1 + st3

    static cudaStream_t sB = nullptr, sC = nullptr;
    static cudaEvent_t evRoot = nullptr, evX0 = nullptr, evConv = nullptr,
                       evBC = nullptr, evH1 = nullptr, evW = nullptr;
    if (!sB) {
        cudaStreamCreateWithFlags(&sB, cudaStreamNonBlocking);
        cudaStreamCreateWithFlags(&sC, cudaStreamNonBlocking);
        cudaEventCreateWithFlags(&evRoot, cudaEventDisableTiming);
        cudaEventCreateWithFlags(&evX0,   cudaEventDisableTiming);
        cudaEventCreateWithFlags(&evConv, cudaEventDisableTiming);
        cudaEventCreateWithFlags(&evBC,   cudaEventDisableTiming);
        cudaEventCreateWithFlags(&evH1,   cudaEventDisableTiming);
        cudaEventCreateWithFlags(&evW,    cudaEventDisableTiming);
        cudaFuncSetAttribute(gV1, cudaFuncAttributeMaxDynamicSharedMemorySize, TG_SMEM_BYTES);
        cudaFuncSetAttribute(gV2, cudaFuncAttributeMaxDynamicSharedMemorySize, TG_SMEM_BYTES);
        cudaFuncSetAttribute(gV3, cudaFuncAttributeMaxDynamicSharedMemorySize, TG_SMEM_BYTES);
        cudaFuncSetAttribute(gV4, cudaFuncAttributeMaxDynamicSharedMemorySize, TG_SMEM_BYTES);
        cudaFuncSetAttribute(gV5, cudaFuncAttributeMaxDynamicSharedMemorySize, TG_SMEM_BYTES);
        cudaFuncSetAttribute(gV6, cudaFuncAttributeMaxDynamicSharedMemorySize, TG_SMEM_BYTES);
    }

    const dim3 blk(256);
    const int NV4 = NTOT * 64;
    cudaStream_t sA = 0;

    cudaEventRecord(evRoot, sA);
    cudaStreamWaitEvent(sB, evRoot, 0);
    cudaStreamWaitEvent(sC, evRoot, 0);

    // ---- Stream C: weight prep ----
    w_split_t<<<(CC * 2 * CC + 255) / 256, blk, 0, sC>>>(W_inproj, p_wiph, p_wipl, CC, 2 * CC);
    make_M_kernel<<<CC, CC, 0, sC>>>(W_dt, W_xproj);
    w_split_t<<<(CC * CC + 255) / 256, blk, 0, sC>>>(W_outproj, p_woph, p_wopl, CC, CC);
    split_arr<<<(CC * 2 * CC / 4 + 255) / 256, blk, 0, sC>>>(W_mlp1, p_wm1h, p_wm1l, CC * 2 * CC / 4);
    split_arr<<<(2 * CC * CC / 4 + 255) / 256, blk, 0, sC>>>(W_mlp2, p_wm2h, p_wm2l, 2 * CC * CC / 4);
    cudaEventRecord(evW, sC);

    // ---- Stream B: degree/dis + W_gcn prep ----
    cudaMemsetAsync(p_deg, 0, NTOT * sizeof(float), sB);
    deg_kernel<<<EE / 256, blk, 0, sB>>>(e_dst);
    dis_kernel<<<NTOT / 256, blk, 0, sB>>>();
    split_arr<<<(CC * CC / 4 + 255) / 256, blk, 0, sB>>>(W_gcn, p_wgh, p_wgl, CC * CC / 4);

    // ---- Stream A: input prep + x0 GEMM ----
    cudaMemsetAsync(p_st1, 0, 2 * CC * sizeof(float), sA);
    cudaMemsetAsync(p_st2, 0, 2 * CC * sizeof(float), sA);
    cudaMemsetAsync(p_st3, 0, 2 * CC * sizeof(float), sA);
    split_arr<<<NTOT * CIN / 4 / 256, blk, 0, sA>>>(node_features, p_nfh, p_nfl, NTOT * CIN / 4);
    split_arr<<<(CIN * CC / 4 + 255) / 256, blk, 0, sA>>>(W_in, p_winh, p_winl, CIN * CC / 4);
    gV1<<<dim3(CC / 128, NTOT / 128), blk, TG_SMEM_BYTES, sA>>>(
        p_nfh, p_nfl, p_winh, p_winl, b_in, nullptr, nullptr, nullptr,
        nullptr, p_x0h, p_x0l, nullptr, NTOT, CC, CIN);
    cudaEventRecord(evX0, sA);

    // ---- Stream B: GCN path ----
    cudaStreamWaitEvent(sB, evX0, 0);
    gV2<<<dim3(CC / 128, NTOT / 128), blk, TG_SMEM_BYTES, sB>>>(
        p_x0h, p_x0l, p_wgh, p_wgl, nullptr, nullptr, nullptr, nullptr,
        p_xw, nullptr, nullptr, nullptr, NTOT, CC, CC);
    init_gcn_kernel<<<NV4 / 256, blk, 0, sB>>>(b_gcn);
    scatter_kernel<<<EE * 64 / 256, blk, 0, sB>>>(e_src, e_dst);
    bn_reduce<true><<<NTOT / 256, blk, 0, sB>>>(p_gcn, p_x0h, p_x0l, p_st1);
    cudaEventRecord(evH1, sB);

    // ---- Stream A: Mamba path ----
    cudaStreamWaitEvent(sA, evW, 0);
    gV2<<<dim3(2 * CC / 128, NTOT / 128), blk, TG_SMEM_BYTES, sA>>>(
        p_x0h, p_x0l, p_wiph, p_wipl, nullptr, nullptr, nullptr, nullptr,
        p_xz, nullptr, nullptr, nullptr, NTOT, 2 * CC, CC);
    conv_silu_kernel<<<NTOT * CC / 256, blk, 0, sA>>>(conv_w, conv_b);
    cudaEventRecord(evConv, sA);

    cudaStreamWaitEvent(sC, evConv, 0);
    gemm_bc_kernel<<<NTOT / 8, blk, 0, sC>>>(W_xproj + DTRANK * CC);
    cudaEventRecord(evBC, sC);

    gV3<<<dim3(CC / 128, NTOT / 128), blk, TG_SMEM_BYTES, sA>>>(
        p_xch, p_xcl, p_mh, p_ml, b_dt, nullptr, nullptr, nullptr,
        p_dt, nullptr, nullptr, nullptr, NTOT, CC, CC);

    cudaStreamWaitEvent(sA, evBC, 0);
    scan_kernel<<<GG * 4, 1024, 0, sA>>>(A_log, Dp);

    gV4<<<dim3(CC / 128, NTOT / 128), blk, TG_SMEM_BYTES, sA>>>(
        p_yh, p_yl, p_woph, p_wopl, nullptr, nullptr, p_x0h, p_x0l,
        p_hm, nullptr, nullptr, p_st2, NTOT, CC, CC);

    cudaStreamWaitEvent(sA, evH1, 0);
    bn12_apply<<<NV4 / 256, blk, 0, sA>>>(
        p_gcn, p_x0h, p_x0l, p_hm, gamma1, beta1, gamma2, beta2,
        p_st1, p_st2, p_o1h, p_o1l);

    gV5<<<dim3(2 * CC / 128, NTOT / 128), blk, TG_SMEM_BYTES, sA>>>(
        p_o1h, p_o1l, p_wm1h, p_wm1l, b_mlp1, nullptr, nullptr, nullptr,
        nullptr, p_mph, nullptr, nullptr, NTOT, 2 * CC, CC);
    gV6<<<dim3(CC / 128, NTOT / 128), blk, TG_SMEM_BYTES, sA>>>(
        p_mph, nullptr, p_wm2h, p_wm2l, b_mlp2, nullptr, p_o1h, p_o1l,
        p_out2, nullptr, nullptr, p_st3, NTOT, CC, 2 * CC);

    bn3_apply<<<NV4 / 256, blk, 0, sA>>>(p_out2, gamma3, beta3, p_st3, out);
}

// round 16
// speedup vs baseline: 1.1407x; 1.1407x over previous
#include <cuda_runtime.h>
#include <cuda_bf16.h>
#include <mma.h>
#include <cstddef>
#include <cstdint>

using namespace nvcuda;

#define NTOT   65536
#define CIN    128
#define CC     256
#define DSTATE 16
#define DCONV  4
#define DTRANK 16
#define GG     32
#define LL     2048
#define EE     131072

typedef __nv_bfloat16 bf16;

// ---------------------------------------------------------------------------
// Device scratch (fp32)
// ---------------------------------------------------------------------------
__device__ __align__(16) float g_xw [NTOT * CC];
__device__ __align__(16) float g_gcn[NTOT * CC];
__device__ __align__(16) float g_xz [NTOT * 2 * CC];
__device__ __align__(16) float g_xcv[NTOT * CC];
__device__ __align__(16) float g_bc [NTOT * 32];
__device__ __align__(16) float g_dt [NTOT * CC];
__device__ __align__(16) float g_hm [NTOT * CC];
__device__ __align__(16) float g_out2[NTOT * CC];
__device__ float g_deg[NTOT];
__device__ float g_dis[NTOT];
__device__ float g_stats1[2 * CC];
__device__ float g_stats2[2 * CC];
__device__ float g_stats3[2 * CC];

// bf16 hi/lo split activations
__device__ __align__(16) bf16 g_nf_h [NTOT * CIN];
__device__ __align__(16) bf16 g_nf_l [NTOT * CIN];
__device__ __align__(16) bf16 g_x0_h [NTOT * CC];
__device__ __align__(16) bf16 g_x0_l [NTOT * CC];
__device__ __align__(16) bf16 g_xcv_h[NTOT * CC];
__device__ __align__(16) bf16 g_xcv_l[NTOT * CC];
__device__ __align__(16) bf16 g_y_h  [NTOT * CC];
__device__ __align__(16) bf16 g_y_l  [NTOT * CC];
__device__ __align__(16) bf16 g_o1_h [NTOT * CC];
__device__ __align__(16) bf16 g_o1_l [NTOT * CC];
__device__ __align__(16) bf16 g_mlp_h[NTOT * 2 * CC];   // single bf16 (no lo)

// bf16 hi/lo split weights, all [K, N] layout
__device__ __align__(16) bf16 g_win_h [CIN * CC];
__device__ __align__(16) bf16 g_win_l [CIN * CC];
__device__ __align__(16) bf16 g_wgcn_h[CC * CC];
__device__ __align__(16) bf16 g_wgcn_l[CC * CC];
__device__ __align__(16) bf16 g_wip_h [CC * 2 * CC];
__device__ __align__(16) bf16 g_wip_l [CC * 2 * CC];
__device__ __align__(16) bf16 g_m_h   [CC * CC];
__device__ __align__(16) bf16 g_m_l   [CC * CC];
__device__ __align__(16) bf16 g_wop_h [CC * CC];
__device__ __align__(16) bf16 g_wop_l [CC * CC];
__device__ __align__(16) bf16 g_wm1_h [CC * 2 * CC];
__device__ __align__(16) bf16 g_wm1_l [CC * 2 * CC];
__device__ __align__(16) bf16 g_wm2_h [2 * CC * CC];
__device__ __align__(16) bf16 g_wm2_l [2 * CC * CC];

__device__ __forceinline__ float act_softplus(float v) {
    return (v > 20.f) ? v : log1pf(__expf(v));
}

__device__ __forceinline__ void split2(float v, bf16& h, bf16& l) {
    h = __float2bfloat16_rn(v);
    l = __float2bfloat16_rn(v - __bfloat162float(h));
}

__device__ __forceinline__ uint32_t smem_u32(const void* p) {
    uint32_t a;
    asm("{ .reg .u64 t; cvta.to.shared.u64 t, %1; cvt.u32.u64 %0, t; }" : "=r"(a) : "l"(p));
    return a;
}

__device__ __forceinline__ float4 recon4(const bf16* h, const bf16* l, size_t idx) {
    __nv_bfloat162 ha = *(const __nv_bfloat162*)&h[idx];
    __nv_bfloat162 hb = *(const __nv_bfloat162*)&h[idx + 2];
    __nv_bfloat162 la = *(const __nv_bfloat162*)&l[idx];
    __nv_bfloat162 lb = *(const __nv_bfloat162*)&l[idx + 2];
    float4 r;
    r.x = __bfloat162float(__low2bfloat16(ha))  + __bfloat162float(__low2bfloat16(la));
    r.y = __bfloat162float(__high2bfloat16(ha)) + __bfloat162float(__high2bfloat16(la));
    r.z = __bfloat162float(__low2bfloat16(hb))  + __bfloat162float(__low2bfloat16(lb));
    r.w = __bfloat162float(__high2bfloat16(hb)) + __bfloat162float(__high2bfloat16(lb));
    return r;
}

// ---------------------------------------------------------------------------
// Split-bf16 tensor-core GEMM: D = AhBh + AhBl (+ AlBh if AHL), fp32 accum.
// Block 128x128, 256 threads (2x4 warps), warp tile 64x32, m16n16k16.
// cp.async 2-stage, K-tile 32. A [M,K], B [K,N].
// RES: 0 none, 1 fp32, 2 bf16 h/l pair.
// OUTB1: single-bf16 output. STATS: fused per-column sum/sumsq.
// ---------------------------------------------------------------------------
#define KT 32
#define A_LDE 40
#define B_LDE 136
#define A_TILE_EL (128 * A_LDE)
#define B_TILE_EL (KT * B_LDE)
#define STAGE_EL (2 * A_TILE_EL + 2 * B_TILE_EL)
#define TG_SMEM_BYTES (2 * STAGE_EL * 2)       // 75776 B
#define STG_LD 36
#define PART_OFF 8192

template <int ACT, bool HASBIAS, int RES, bool OUTF32, bool OUTSPLIT, bool OUTB1,
          bool STATS, bool AHL>
__global__ void __launch_bounds__(256, 2)
bgemm_k(const bf16* __restrict__ Ah, const bf16* __restrict__ Al,
        const bf16* __restrict__ Bh, const bf16* __restrict__ Bl,
        const float* __restrict__ bias,
        const float* __restrict__ resF,
        const bf16* __restrict__ resH, const bf16* __restrict__ resL,
        float* __restrict__ outF, bf16* __restrict__ outH, bf16* __restrict__ outL,
        float* __restrict__ stats,
        int M, int Nout, int K)
{
    extern __shared__ bf16 smem[];

    const int tid = threadIdx.x;
    const int warp = tid >> 5;
    const int lane = tid & 31;
    const int warp_m = warp >> 2;
    const int warp_n = warp & 3;
    const int m0 = blockIdx.y * 128;
    const int n0 = blockIdx.x * 128;

    wmma::fragment<wmma::accumulator, 16, 16, 16, float> cf[4][2];
#pragma unroll
    for (int i = 0; i < 4; i++)
#pragma unroll
        for (int j = 0; j < 2; j++) wmma::fill_fragment(cf[i][j], 0.f);

    auto issue_tile = [&](int kt, int buf) {
        bf16* sAh = smem + buf * STAGE_EL;
        bf16* sAl = sAh + A_TILE_EL;
        bf16* sBh = sAl + A_TILE_EL;
        bf16* sBl = sBh + B_TILE_EL;
#pragma unroll
        for (int it = 0; it < 2; it++) {
            int i = it * 256 + tid;
            int r = i >> 2, c = i & 3;
            size_t src = (size_t)(m0 + r) * K + kt + c * 8;
            asm volatile("cp.async.ca.shared.global [%0], [%1], 16;"
                         :: "r"(smem_u32(&sAh[r * A_LDE + c * 8])), "l"(Ah + src));
            if (AHL)
                asm volatile("cp.async.ca.shared.global [%0], [%1], 16;"
                             :: "r"(smem_u32(&sAl[r * A_LDE + c * 8])), "l"(Al + src));
        }
#pragma unroll
        for (int it = 0; it < 2; it++) {
            int i = it * 256 + tid;
            int r = i >> 4, c = i & 15;
            size_t src = (size_t)(kt + r) * Nout + n0 + c * 8;
            asm volatile("cp.async.ca.shared.global [%0], [%1], 16;"
                         :: "r"(smem_u32(&sBh[r * B_LDE + c * 8])), "l"(Bh + src));
            asm volatile("cp.async.ca.shared.global [%0], [%1], 16;"
                         :: "r"(smem_u32(&sBl[r * B_LDE + c * 8])), "l"(Bl + src));
        }
        asm volatile("cp.async.commit_group;");
    };

    const int nk = K / KT;
    issue_tile(0, 0);

    for (int i = 0; i < nk; i++) {
        const bool has_next = (i + 1) < nk;
        if (has_next) issue_tile((i + 1) * KT, (i + 1) & 1);

        if (has_next) asm volatile("cp.async.wait_group 1;");
        else          asm volatile("cp.async.wait_group 0;");
        __syncthreads();

        const bf16* sAh = smem + (i & 1) * STAGE_EL;
        const bf16* sAl = sAh + A_TILE_EL;
        const bf16* sBh = sAl + A_TILE_EL;
        const bf16* sBl = sBh + B_TILE_EL;

#pragma unroll
        for (int ks = 0; ks < KT; ks += 16) {
            wmma::fragment<wmma::matrix_b, 16, 16, 16, bf16, wmma::row_major> bh[2], bl[2];
#pragma unroll
            for (int j = 0; j < 2; j++) {
                wmma::load_matrix_sync(bh[j], &sBh[ks * B_LDE + warp_n * 32 + j * 16], B_LDE);
                wmma::load_matrix_sync(bl[j], &sBl[ks * B_LDE + warp_n * 32 + j * 16], B_LDE);
            }
#pragma unroll
            for (int x = 0; x < 4; x++) {
                wmma::fragment<wmma::matrix_a, 16, 16, 16, bf16, wmma::row_major> ah, al;
                wmma::load_matrix_sync(ah, &sAh[(warp_m * 64 + x * 16) * A_LDE + ks], A_LDE);
                if (AHL)
                    wmma::load_matrix_sync(al, &sAl[(warp_m * 64 + x * 16) * A_LDE + ks], A_LDE);
#pragma unroll
                for (int j = 0; j < 2; j++) {
                    wmma::mma_sync(cf[x][j], ah, bh[j], cf[x][j]);
                    wmma::mma_sync(cf[x][j], ah, bl[j], cf[x][j]);
                    if (AHL) wmma::mma_sync(cf[x][j], al, bh[j], cf[x][j]);
                }
            }
        }
        __syncthreads();
    }

    float* fs = reinterpret_cast<float*>(smem);
    float* stg = fs + warp * (16 * STG_LD);
    float* mp = fs + PART_OFF + tid * 33;
    const int erow = lane >> 1;
    const int ecol0 = (lane & 1) * 16;

    if (STATS) {
#pragma unroll
        for (int i = 0; i < 32; i++) mp[i] = 0.f;
    }

#pragma unroll
    for (int x = 0; x < 4; x++) {
        wmma::store_matrix_sync(stg,      cf[x][0], STG_LD, wmma::mem_row_major);
        wmma::store_matrix_sync(stg + 16, cf[x][1], STG_LD, wmma::mem_row_major);
        __syncwarp();
        const int grow = m0 + warp_m * 64 + x * 16 + erow;
#pragma unroll
        for (int c4 = 0; c4 < 16; c4 += 4) {
            const int lcol = ecol0 + c4;
            const int gcol = n0 + warp_n * 32 + lcol;
            float4 v = *(float4*)&stg[erow * STG_LD + lcol];
            if (HASBIAS) {
                float4 bb = *(const float4*)&bias[gcol];
                v.x += bb.x; v.y += bb.y; v.z += bb.z; v.w += bb.w;
            }
            if (ACT == 1) {
                v.x = fmaxf(v.x, 0.f); v.y = fmaxf(v.y, 0.f);
                v.z = fmaxf(v.z, 0.f); v.w = fmaxf(v.w, 0.f);
            } else if (ACT == 2) {
                v.x = act_softplus(v.x); v.y = act_softplus(v.y);
                v.z = act_softplus(v.z); v.w = act_softplus(v.w);
            }
            const size_t oidx = (size_t)grow * Nout + gcol;
            if (RES == 1) {
                float4 rr = *(const float4*)&resF[oidx];
                v.x += rr.x; v.y += rr.y; v.z += rr.z; v.w += rr.w;
            } else if (RES == 2) {
                float4 rr = recon4(resH, resL, oidx);
                v.x += rr.x; v.y += rr.y; v.z += rr.z; v.w += rr.w;
            }
            if (STATS) {
                mp[c4 + 0] += v.x; mp[c4 + 1] += v.y;
                mp[c4 + 2] += v.z; mp[c4 + 3] += v.w;
                mp[16 + c4 + 0] += v.x * v.x; mp[16 + c4 + 1] += v.y * v.y;
                mp[16 + c4 + 2] += v.z * v.z; mp[16 + c4 + 3] += v.w * v.w;
            }
            if (OUTF32) *(float4*)&outF[oidx] = v;
            if (OUTSPLIT) {
                bf16 h0, l0, h1, l1, h2, l2, h3, l3;
                split2(v.x, h0, l0); split2(v.y, h1, l1);
                split2(v.z, h2, l2); split2(v.w, h3, l3);
                __nv_bfloat162 ha = {h0, h1}, hb = {h2, h3};
                __nv_bfloat162 la = {l0, l1}, lb = {l2, l3};
                *(__nv_bfloat162*)&outH[oidx]     = ha;
                *(__nv_bfloat162*)&outH[oidx + 2] = hb;
                *(__nv_bfloat162*)&outL[oidx]     = la;
                *(__nv_bfloat162*)&outL[oidx + 2] = lb;
            }
            if (OUTB1) {
                __nv_bfloat162 ha = __floats2bfloat162_rn(v.x, v.y);
                __nv_bfloat162 hb = __floats2bfloat162_rn(v.z, v.w);
                *(__nv_bfloat162*)&outH[oidx]     = ha;
                *(__nv_bfloat162*)&outH[oidx + 2] = hb;
            }
        }
        __syncwarp();
    }

    if (STATS) {
        __syncthreads();
        const int c = tid >> 1, s = tid & 1;
        const int wn = c >> 5, ch = (c >> 4) & 1, li = c & 15;
        float tot = 0.f;
#pragma unroll
        for (int wm = 0; wm < 2; wm++)
#pragma unroll
            for (int er = 0; er < 16; er++) {
                int ct = (wm * 4 + wn) * 32 + er * 2 + ch;
                tot += fs[PART_OFF + ct * 33 + s * 16 + li];
            }
        atomicAdd(&stats[s * CC + n0 + c], tot);
    }
}

// ---------------------------------------------------------------------------
// Split kernels
// ---------------------------------------------------------------------------
__global__ void split_arr(const float* __restrict__ src, bf16* __restrict__ oh,
                          bf16* __restrict__ ol, int n4) {
    int i = blockIdx.x * 256 + threadIdx.x;
    if (i >= n4) return;
    float4 v = *(const float4*)&src[(size_t)i * 4];
    size_t b = (size_t)i * 4;
    split2(v.x, oh[b + 0], ol[b + 0]);
    split2(v.y, oh[b + 1], ol[b + 1]);
    split2(v.z, oh[b + 2], ol[b + 2]);
    split2(v.w, oh[b + 3], ol[b + 3]);
}

__global__ void w_split_t(const float* __restrict__ W, bf16* __restrict__ oh,
                          bf16* __restrict__ ol, int Kk, int Nn) {
    int idx = blockIdx.x * 256 + threadIdx.x;
    if (idx >= Kk * Nn) return;
    int k = idx / Nn, n = idx % Nn;
    split2(W[(size_t)n * Kk + k], oh[idx], ol[idx]);
}

__global__ void make_M_kernel(const float* __restrict__ W_dt,
                              const float* __restrict__ W_xproj) {
    int c = blockIdx.x, d = threadIdx.x;
    float s = 0.f;
#pragma unroll
    for (int r = 0; r < DTRANK; r++)
        s += W_dt[c * DTRANK + r] * W_xproj[r * CC + d];
    split2(s, g_m_h[d * CC + c], g_m_l[d * CC + c]);
}

// ---------------------------------------------------------------------------
// GCN helpers
// ---------------------------------------------------------------------------
__global__ void deg_kernel(const int* __restrict__ dst) {
    int e = blockIdx.x * 256 + threadIdx.x;
    if (e < EE) atomicAdd(&g_deg[dst[e]], 1.0f);
}

__global__ void dis_kernel() {
    int n = blockIdx.x * 256 + threadIdx.x;
    if (n < NTOT) g_dis[n] = rsqrtf(g_deg[n] + 1.0f);
}

__global__ void init_gcn_kernel(const float* __restrict__ b_gcn) {
    int idx = blockIdx.x * 256 + threadIdx.x;
    int n = idx >> 6;
    int c4 = (idx & 63) << 2;
    float w = g_dis[n]; w *= w;
    float4 xv = *(const float4*)&g_xw[(size_t)n * CC + c4];
    float4 bb = *(const float4*)&b_gcn[c4];
    float4 o;
    o.x = bb.x + xv.x * w; o.y = bb.y + xv.y * w;
    o.z = bb.z + xv.z * w; o.w = bb.w + xv.w * w;
    *(float4*)&g_gcn[(size_t)n * CC + c4] = o;
}

__global__ void scatter_kernel(const int* __restrict__ src, const int* __restrict__ dst) {
    int t = blockIdx.x * 256 + threadIdx.x;
    int e = t >> 6;
    int c4 = (t & 63) << 2;
    int s = src[e], d = dst[e];
    float w = g_dis[s] * g_dis[d];
    float4 v = *(const float4*)&g_xw[(size_t)s * CC + c4];
    float* o = &g_gcn[(size_t)d * CC + c4];
    asm volatile("red.global.add.v4.f32 [%0], {%1, %2, %3, %4};"
                 :: "l"(o), "f"(v.x * w), "f"(v.y * w), "f"(v.z * w), "f"(v.w * w)
                 : "memory");
}

// ---------------------------------------------------------------------------
// BatchNorm
// ---------------------------------------------------------------------------
template <bool HASB2>
__global__ void bn_reduce(const float* __restrict__ A,
                          const bf16* __restrict__ Bh, const bf16* __restrict__ Bl,
                          float* __restrict__ stats) {
    int c = threadIdx.x;
    int r0 = blockIdx.x * 256;
    float s = 0.f, s2 = 0.f;
    for (int r = 0; r < 256; r++) {
        size_t idx = (size_t)(r0 + r) * CC + c;
        float v = A[idx];
        if (HASB2)
            v += __bfloat162float(Bh[idx]) + __bfloat162float(Bl[idx]);
        s += v; s2 += v * v;
    }
    atomicAdd(&stats[c], s);
    atomicAdd(&stats[CC + c], s2);
}

// Fused BN1+BN2 apply: o1 = norm1(gcn + x0) + norm2(hm)  [hm has +x0]
__global__ void bn12_apply(const float* __restrict__ gcn,
                           const bf16* __restrict__ x0h, const bf16* __restrict__ x0l,
                           const float* __restrict__ hm,
                           const float* __restrict__ g1, const float* __restrict__ b1,
                           const float* __restrict__ g2, const float* __restrict__ b2,
                           const float* __restrict__ st1, const float* __restrict__ st2,
                           bf16* __restrict__ oh, bf16* __restrict__ ol)
{
    int idx = blockIdx.x * 256 + threadIdx.x;
    int c4 = (idx & 63) << 2;
    const float invN = 1.0f / NTOT;

    float4 a = *(const float4*)&gcn[(size_t)idx * 4];
    float4 x = recon4(x0h, x0l, (size_t)idx * 4);
    a.x += x.x; a.y += x.y; a.z += x.z; a.w += x.w;
    float4 b = *(const float4*)&hm[(size_t)idx * 4];

    float4 sm1 = *(const float4*)&st1[c4];
    float4 sq1 = *(const float4*)&st1[CC + c4];
    float4 sm2 = *(const float4*)&st2[c4];
    float4 sq2 = *(const float4*)&st2[CC + c4];
    float4 gm1 = *(const float4*)&g1[c4];
    float4 bt1 = *(const float4*)&b1[c4];
    float4 gm2 = *(const float4*)&g2[c4];
    float4 bt2 = *(const float4*)&b2[c4];

    float4 o;
    {
        float m1 = sm1.x * invN, m2 = sm2.x * invN;
        float r1 = rsqrtf(sq1.x * invN - m1 * m1 + 1e-5f);
        float r2 = rsqrtf(sq2.x * invN - m2 * m2 + 1e-5f);
        o.x = (a.x - m1) * r1 * gm1.x + bt1.x + (b.x - m2) * r2 * gm2.x + bt2.x;
    }
    {
        float m1 = sm1.y * invN, m2 = sm2.y * invN;
        float r1 = rsqrtf(sq1.y * invN - m1 * m1 + 1e-5f);
        float r2 = rsqrtf(sq2.y * invN - m2 * m2 + 1e-5f);
        o.y = (a.y - m1) * r1 * gm1.y + bt1.y + (b.y - m2) * r2 * gm2.y + bt2.y;
    }
    {
        float m1 = sm1.z * invN, m2 = sm2.z * invN;
        float r1 = rsqrtf(sq1.z * invN - m1 * m1 + 1e-5f);
        float r2 = rsqrtf(sq2.z * invN - m2 * m2 + 1e-5f);
        o.z = (a.z - m1) * r1 * gm1.z + bt1.z + (b.z - m2) * r2 * gm2.z + bt2.z;
    }
    {
        float m1 = sm1.w * invN, m2 = sm2.w * invN;
        float r1 = rsqrtf(sq1.w * invN - m1 * m1 + 1e-5f);
        float r2 = rsqrtf(sq2.w * invN - m2 * m2 + 1e-5f);
        o.w = (a.w - m1) * r1 * gm1.w + bt1.w + (b.w - m2) * r2 * gm2.w + bt2.w;
    }

    size_t base = (size_t)idx * 4;
    split2(o.x, oh[base + 0], ol[base + 0]);
    split2(o.y, oh[base + 1], ol[base + 1]);
    split2(o.z, oh[base + 2], ol[base + 2]);
    split2(o.w, oh[base + 3], ol[base + 3]);
}

__global__ void bn3_apply(const float* __restrict__ A,
                          const float* __restrict__ gamma, const float* __restrict__ beta,
                          const float* __restrict__ stats, float* __restrict__ out)
{
    int idx = blockIdx.x * 256 + threadIdx.x;
    int c4 = (idx & 63) << 2;
    const float invN = 1.0f / NTOT;
    float4 v = *(const float4*)&A[(size_t)idx * 4];
    float4 sm = *(const float4*)&stats[c4];
    float4 sq = *(const float4*)&stats[CC + c4];
    float4 gm = *(const float4*)&gamma[c4];
    float4 bt = *(const float4*)&beta[c4];
    float4 m, r, o;
    m.x = sm.x * invN; m.y = sm.y * invN; m.z = sm.z * invN; m.w = sm.w * invN;
    r.x = rsqrtf(sq.x * invN - m.x * m.x + 1e-5f);
    r.y = rsqrtf(sq.y * invN - m.y * m.y + 1e-5f);
    r.z = rsqrtf(sq.z * invN - m.z * m.z + 1e-5f);
    r.w = rsqrtf(sq.w * invN - m.w * m.w + 1e-5f);
    o.x = fmaxf((v.x - m.x) * r.x * gm.x + bt.x, 0.f);
    o.y = fmaxf((v.y - m.y) * r.y * gm.y + bt.y, 0.f);
    o.z = fmaxf((v.z - m.z) * r.z * gm.z + bt.z, 0.f);
    o.w = fmaxf((v.w - m.w) * r.w * gm.w + bt.w, 0.f);
    *(float4*)&out[(size_t)idx * 4] = o;
}

// ---------------------------------------------------------------------------
// Mamba pieces
// ---------------------------------------------------------------------------
__global__ void conv_silu_kernel(const float* __restrict__ conv_w,
                                 const float* __restrict__ conv_b) {
    int idx = blockIdx.x * 256 + threadIdx.x;
    int n = idx >> 8;
    int c = idx & 255;
    int l = n & (LL - 1);
    float acc = conv_b[c];
#pragma unroll
    for (int kk = 0; kk < DCONV; kk++) {
        int l2 = l + kk - (DCONV - 1);
        if (l2 >= 0)
            acc += g_xz[(size_t)(n + kk - (DCONV - 1)) * (2 * CC) + c] * conv_w[c * DCONV + kk];
    }
    float sg = __fdividef(1.f, 1.f + __expf(-acc));
    float r = acc * sg;
    size_t o = (size_t)n * CC + c;
    g_xcv[o] = r;
    split2(r, g_xcv_h[o], g_xcv_l[o]);
}

__global__ void __launch_bounds__(256) gemm_bc_kernel(const float* __restrict__ W) {
    __shared__ float Ws[32][257];
    __shared__ float xs[8][256];
    int tid = threadIdx.x;
    for (int i = tid; i < 32 * 256; i += 256) Ws[i >> 8][i & 255] = W[i];
    int r0 = blockIdx.x * 8;
    for (int i = tid; i < 8 * 256; i += 256)
        xs[i >> 8][i & 255] = g_xcv[(size_t)(r0 + (i >> 8)) * CC + (i & 255)];
    __syncthreads();
    int r = tid >> 5, j = tid & 31;
    float acc = 0.f;
#pragma unroll 8
    for (int k = 0; k < 256; k++) acc = fmaf(xs[r][k], Ws[j][k], acc);
    g_bc[(size_t)(r0 + r) * 32 + j] = acc;
}

__global__ void __launch_bounds__(1024) scan_kernel(const float* __restrict__ A_log,
                                                    const float* __restrict__ Dp) {
    int g = blockIdx.x >> 2;
    int cb = blockIdx.x & 3;
    int tid = threadIdx.x;
    int chl = tid >> 4;
    int n = tid & 15;
    int d = cb * 64 + chl;

    float An = -expf(A_log[d * DSTATE + n]);
    float Dd = Dp[d];

    const float* dtp = g_dt + (size_t)g * LL * CC + d;
    const float* xp  = g_xcv + (size_t)g * LL * CC + d;
    const float* bp  = g_bc + (size_t)g * LL * 32 + n;
    const float* cp  = bp + 16;
    const float* zp  = g_xz + (size_t)g * LL * (2 * CC) + CC + d;
    bf16* yh = g_y_h + (size_t)g * LL * CC + d;
    bf16* yl = g_y_l + (size_t)g * LL * CC + d;

    float h = 0.f;
    float dtv = dtp[0], xv = xp[0], Bn = bp[0], Cn = cp[0];
    float zv = (n == 0) ? zp[0] : 0.f;

    for (int t = 0; t < LL; t++) {
        float dtn = 0.f, xn = 0.f, Bn2 = 0.f, Cn2 = 0.f, zn = 0.f;
        if (t + 1 < LL) {
            dtn = dtp[(size_t)(t + 1) * CC];
            xn  = xp[(size_t)(t + 1) * CC];
            Bn2 = bp[(size_t)(t + 1) * 32];
            Cn2 = cp[(size_t)(t + 1) * 32];
            if (n == 0) zn = zp[(size_t)(t + 1) * (2 * CC)];
        }
        float e = __expf(dtv * An);
        float dx = dtv * xv;
        h = fmaf(e, h, dx * Bn);
        float p = h * Cn;
        p += __shfl_xor_sync(0xffffffffu, p, 1);
        p += __shfl_xor_sync(0xffffffffu, p, 2);
        p += __shfl_xor_sync(0xffffffffu, p, 4);
        p += __shfl_xor_sync(0xffffffffu, p, 8);
        if (n == 0) {
            float sg = __fdividef(zv, 1.f + __expf(-zv));
            float yv = (p + xv * Dd) * sg;
            bf16 hh, lll;
            split2(yv, hh, lll);
            yh[(size_t)t * CC] = hh;
            yl[(size_t)t * CC] = lll;
        }
        dtv = dtn; xv = xn; Bn = Bn2; Cn = Cn2; zv = zn;
    }
}

// ---------------------------------------------------------------------------
// Host launcher
// ---------------------------------------------------------------------------
extern "C" void kernel_launch(void* const* d_in, const int* in_sizes, int n_in,
                              void* d_out, int out_size)
{
    const float* node_features = (const float*)d_in[0];
    const int*   edge_index    = (const int*)d_in[1];
    const float* W_in    = (const float*)d_in[3];
    const float* b_in    = (const float*)d_in[4];
    const float* W_gcn   = (const float*)d_in[5];
    const float* b_gcn   = (const float*)d_in[6];
    const float* gamma1  = (const float*)d_in[7];
    const float* beta1   = (const float*)d_in[8];
    const float* gamma2  = (const float*)d_in[9];
    const float* beta2   = (const float*)d_in[10];
    const float* gamma3  = (const float*)d_in[11];
    const float* beta3   = (const float*)d_in[12];
    const float* W_inproj = (const float*)d_in[13];
    const float* conv_w  = (const float*)d_in[14];
    const float* conv_b  = (const float*)d_in[15];
    const float* W_xproj = (const float*)d_in[16];
    const float* W_dt    = (const float*)d_in[17];
    const float* b_dt    = (const float*)d_in[18];
    const float* A_log   = (const float*)d_in[19];
    const float* Dp      = (const float*)d_in[20];
    const float* W_outproj = (const float*)d_in[21];
    const float* W_mlp1  = (const float*)d_in[22];
    const float* b_mlp1  = (const float*)d_in[23];
    const float* W_mlp2  = (const float*)d_in[24];
    const float* b_mlp2  = (const float*)d_in[25];
    float* out = (float*)d_out;

    const int* e_src = edge_index;
    const int* e_dst = edge_index + EE;

    float *p_xw, *p_xz, *p_dt, *p_hm, *p_out2, *p_gcn, *p_deg;
    float *p_st1, *p_st2, *p_st3;
    bf16 *p_nfh, *p_nfl, *p_x0h, *p_x0l, *p_xch, *p_xcl, *p_yh, *p_yl,
         *p_o1h, *p_o1l, *p_mph;
    bf16 *p_winh, *p_winl, *p_wgh, *p_wgl, *p_wiph, *p_wipl, *p_mh, *p_ml,
         *p_woph, *p_wopl, *p_wm1h, *p_wm1l, *p_wm2h, *p_wm2l;
    cudaGetSymbolAddress((void**)&p_xw,   g_xw);
    cudaGetSymbolAddress((void**)&p_xz,   g_xz);
    cudaGetSymbolAddress((void**)&p_dt,   g_dt);
    cudaGetSymbolAddress((void**)&p_hm,   g_hm);
    cudaGetSymbolAddress((void**)&p_out2, g_out2);
    cudaGetSymbolAddress((void**)&p_gcn,  g_gcn);
    cudaGetSymbolAddress((void**)&p_deg,  g_deg);
    cudaGetSymbolAddress((void**)&p_st1,  g_stats1);
    cudaGetSymbolAddress((void**)&p_st2,  g_stats2);
    cudaGetSymbolAddress((void**)&p_st3,  g_stats3);
    cudaGetSymbolAddress((void**)&p_nfh,  g_nf_h);
    cudaGetSymbolAddress((void**)&p_nfl,  g_nf_l);
    cudaGetSymbolAddress((void**)&p_x0h,  g_x0_h);
    cudaGetSymbolAddress((void**)&p_x0l,  g_x0_l);
    cudaGetSymbolAddress((void**)&p_xch,  g_xcv_h);
    cudaGetSymbolAddress((void**)&p_xcl,  g_xcv_l);
    cudaGetSymbolAddress((void**)&p_yh,   g_y_h);
    cudaGetSymbolAddress((void**)&p_yl,   g_y_l);
    cudaGetSymbolAddress((void**)&p_o1h,  g_o1_h);
    cudaGetSymbolAddress((void**)&p_o1l,  g_o1_l);
    cudaGetSymbolAddress((void**)&p_mph,  g_mlp_h);
    cudaGetSymbolAddress((void**)&p_winh, g_win_h);
    cudaGetSymbolAddress((void**)&p_winl, g_win_l);
    cudaGetSymbolAddress((void**)&p_wgh,  g_wgcn_h);
    cudaGetSymbolAddress((void**)&p_wgl,  g_wgcn_l);
    cudaGetSymbolAddress((void**)&p_wiph, g_wip_h);
    cudaGetSymbolAddress((void**)&p_wipl, g_wip_l);
    cudaGetSymbolAddress((void**)&p_mh,   g_m_h);
    cudaGetSymbolAddress((void**)&p_ml,   g_m_l);
    cudaGetSymbolAddress((void**)&p_woph, g_wop_h);
    cudaGetSymbolAddress((void**)&p_wopl, g_wop_l);
    cudaGetSymbolAddress((void**)&p_wm1h, g_wm1_h);
    cudaGetSymbolAddress((void**)&p_wm1l, g_wm1_l);
    cudaGetSymbolAddress((void**)&p_wm2h, g_wm2_h);
    cudaGetSymbolAddress((void**)&p_wm2l, g_wm2_l);

    // <ACT, HASBIAS, RES, OUTF32, OUTSPLIT, OUTB1, STATS, AHL>
    auto* gV1 = bgemm_k<0, true,  0, false, true,  false, false, true >;  // x0 split
    auto* gV2 = bgemm_k<0, false, 0, true,  false, false, false, true >;  // xw, xz
    auto* gV3 = bgemm_k<2, true,  0, true,  false, false, false, true >;  // dt
    auto* gV4 = bgemm_k<0, false, 2, true,  false, false, true,  true >;  // outproj + x0 + st2
    auto* gV5 = bgemm_k<1, true,  0, false, false, true,  false, true >;  // mlp1 -> single bf16
    auto* gV6 = bgemm_k<0, true,  2, true,  false, false, true,  false>;  // mlp2 (A single) + o1 + st3

    static cudaStream_t sB = nullptr, sC = nullptr;
    static cudaEvent_t evRoot = nullptr, evX0 = nullptr, evConv = nullptr,
                       evBC = nullptr, evH1 = nullptr, evW = nullptr;
    if (!sB) {
        cudaStreamCreateWithFlags(&sB, cudaStreamNonBlocking);
        cudaStreamCreateWithFlags(&sC, cudaStreamNonBlocking);
        cudaEventCreateWithFlags(&evRoot, cudaEventDisableTiming);
        cudaEventCreateWithFlags(&evX0,   cudaEventDisableTiming);
        cudaEventCreateWithFlags(&evConv, cudaEventDisableTiming);
        cudaEventCreateWithFlags(&evBC,   cudaEventDisableTiming);
        cudaEventCreateWithFlags(&evH1,   cudaEventDisableTiming);
        cudaEventCreateWithFlags(&evW,    cudaEventDisableTiming);
        cudaFuncSetAttribute(gV1, cudaFuncAttributeMaxDynamicSharedMemorySize, TG_SMEM_BYTES);
        cudaFuncSetAttribute(gV2, cudaFuncAttributeMaxDynamicSharedMemorySize, TG_SMEM_BYTES);
        cudaFuncSetAttribute(gV3, cudaFuncAttributeMaxDynamicSharedMemorySize, TG_SMEM_BYTES);
        cudaFuncSetAttribute(gV4, cudaFuncAttributeMaxDynamicSharedMemorySize, TG_SMEM_BYTES);
        cudaFuncSetAttribute(gV5, cudaFuncAttributeMaxDynamicSharedMemorySize, TG_SMEM_BYTES);
        cudaFuncSetAttribute(gV6, cudaFuncAttributeMaxDynamicSharedMemorySize, TG_SMEM_BYTES);
    }

    const dim3 blk(256);
    const int NV4 = NTOT * 64;
    cudaStream_t sA = 0;

    cudaEventRecord(evRoot, sA);
    cudaStreamWaitEvent(sB, evRoot, 0);
    cudaStreamWaitEvent(sC, evRoot, 0);

    // ---- Stream C: weight prep ----
    w_split_t<<<(CC * 2 * CC + 255) / 256, blk, 0, sC>>>(W_inproj, p_wiph, p_wipl, CC, 2 * CC);
    make_M_kernel<<<CC, CC, 0, sC>>>(W_dt, W_xproj);
    w_split_t<<<(CC * CC + 255) / 256, blk, 0, sC>>>(W_outproj, p_woph, p_wopl, CC, CC);
    split_arr<<<(CC * 2 * CC / 4 + 255) / 256, blk, 0, sC>>>(W_mlp1, p_wm1h, p_wm1l, CC * 2 * CC / 4);
    split_arr<<<(2 * CC * CC / 4 + 255) / 256, blk, 0, sC>>>(W_mlp2, p_wm2h, p_wm2l, 2 * CC * CC / 4);
    cudaEventRecord(evW, sC);

    // ---- Stream B: degree/dis + W_gcn prep ----
    cudaMemsetAsync(p_deg, 0, NTOT * sizeof(float), sB);
    deg_kernel<<<EE / 256, blk, 0, sB>>>(e_dst);
    dis_kernel<<<NTOT / 256, blk, 0, sB>>>();
    split_arr<<<(CC * CC / 4 + 255) / 256, blk, 0, sB>>>(W_gcn, p_wgh, p_wgl, CC * CC / 4);

    // ---- Stream A: input prep + x0 GEMM ----
    cudaMemsetAsync(p_st1, 0, 2 * CC * sizeof(float), sA);
    cudaMemsetAsync(p_st2, 0, 2 * CC * sizeof(float), sA);
    cudaMemsetAsync(p_st3, 0, 2 * CC * sizeof(float), sA);
    split_arr<<<NTOT * CIN / 4 / 256, blk, 0, sA>>>(node_features, p_nfh, p_nfl, NTOT * CIN / 4);
    split_arr<<<(CIN * CC / 4 + 255) / 256, blk, 0, sA>>>(W_in, p_winh, p_winl, CIN * CC / 4);
    gV1<<<dim3(CC / 128, NTOT / 128), blk, TG_SMEM_BYTES, sA>>>(
        p_nfh, p_nfl, p_winh, p_winl, b_in, nullptr, nullptr, nullptr,
        nullptr, p_x0h, p_x0l, nullptr, NTOT, CC, CIN);
    cudaEventRecord(evX0, sA);

    // ---- Stream B: GCN path ----
    cudaStreamWaitEvent(sB, evX0, 0);
    gV2<<<dim3(CC / 128, NTOT / 128), blk, TG_SMEM_BYTES, sB>>>(
        p_x0h, p_x0l, p_wgh, p_wgl, nullptr, nullptr, nullptr, nullptr,
        p_xw, nullptr, nullptr, nullptr, NTOT, CC, CC);
    init_gcn_kernel<<<NV4 / 256, blk, 0, sB>>>(b_gcn);
    scatter_kernel<<<EE * 64 / 256, blk, 0, sB>>>(e_src, e_dst);
    bn_reduce<true><<<NTOT / 256, blk, 0, sB>>>(p_gcn, p_x0h, p_x0l, p_st1);
    cudaEventRecord(evH1, sB);

    // ---- Stream A: Mamba path ----
    cudaStreamWaitEvent(sA, evW, 0);
    gV2<<<dim3(2 * CC / 128, NTOT / 128), blk, TG_SMEM_BYTES, sA>>>(
        p_x0h, p_x0l, p_wiph, p_wipl, nullptr, nullptr, nullptr, nullptr,
        p_xz, nullptr, nullptr, nullptr, NTOT, 2 * CC, CC);
    conv_silu_kernel<<<NTOT * CC / 256, blk, 0, sA>>>(conv_w, conv_b);
    cudaEventRecord(evConv, sA);

    cudaStreamWaitEvent(sC, evConv, 0);
    gemm_bc_kernel<<<NTOT / 8, blk, 0, sC>>>(W_xproj + DTRANK * CC);
    cudaEventRecord(evBC, sC);

    gV3<<<dim3(CC / 128, NTOT / 128), blk, TG_SMEM_BYTES, sA>>>(
        p_xch, p_xcl, p_mh, p_ml, b_dt, nullptr, nullptr, nullptr,
        p_dt, nullptr, nullptr, nullptr, NTOT, CC, CC);

    cudaStreamWaitEvent(sA, evBC, 0);
    scan_kernel<<<GG * 4, 1024, 0, sA>>>(A_log, Dp);

    gV4<<<dim3(CC / 128, NTOT / 128), blk, TG_SMEM_BYTES, sA>>>(
        p_yh, p_yl, p_woph, p_wopl, nullptr, nullptr, p_x0h, p_x0l,
        p_hm, nullptr, nullptr, p_st2, NTOT, CC, CC);

    cudaStreamWaitEvent(sA, evH1, 0);
    bn12_apply<<<NV4 / 256, blk, 0, sA>>>(
        p_gcn, p_x0h, p_x0l, p_hm, gamma1, beta1, gamma2, beta2,
        p_st1, p_st2, p_o1h, p_o1l);

    gV5<<<dim3(2 * CC / 128, NTOT / 128), blk, TG_SMEM_BYTES, sA>>>(
        p_o1h, p_o1l, p_wm1h, p_wm1l, b_mlp1, nullptr, nullptr, nullptr,
        nullptr, p_mph, nullptr, nullptr, NTOT, 2 * CC, CC);
    gV6<<<dim3(CC / 128, NTOT / 128), blk, TG_SMEM_BYTES, sA>>>(
        p_mph, nullptr, p_wm2h, p_wm2l, b_mlp2, nullptr, p_o1h, p_o1l,
        p_out2, nullptr, nullptr, p_st3, NTOT, CC, 2 * CC);

    bn3_apply<<<NV4 / 256, blk, 0, sA>>>(p_out2, gamma3, beta3, p_st3, out);
}